// round 14
// baseline (speedup 1.0000x reference)
#include <cuda_runtime.h>
#include <cuda.h>
#include <cuda_fp16.h>
#include <cstdint>
#include <cstddef>

// Problem dims (fixed by the dataset)
#define BATCH 4
#define MDIM 2048
#define NDIM 2048
#define KDIM 2048

// GEMM tiling: R13 geometry (128x64 tile, 8 warps 4Mx2N, warp tile 32x32,
// lockstep pipeline, occupancy 3 = 24 warps/SM, dynamic tile stealing),
// now with a 3-deep TMA pipeline (fits: 3 CTAs x 74.75KB = 224KB/SM).
#define TILE_M 128
#define TILE_N 64
#define KC 64                    // K per chunk: 1 SW128 atom
#define CPT 32                   // chunks per tile
#define STAGES 3
#define NTILES_TOTAL 2048        // 32 * 16 * 4
#define GRID_X 456               // 3 * 152 SMs (GB300)

// Per-stage SMEM: A 16KB + B 8KB
#define OFF_AH 0
#define OFF_BH 16384
#define STAGE_BYTES 24576
#define SMEM_CTRL 1024
#define SMEM_TOTAL (SMEM_CTRL + STAGES * STAGE_BYTES)   // 74752 (x3 CTAs/SM)

// ---------------------------------------------------------------------------
// Scratch: fp16 of A [B,M,K]; B transposed to [B,N,K] (K-major)
// ---------------------------------------------------------------------------
__device__ alignas(1024) __half g_Ah[(size_t)BATCH * MDIM * KDIM];
__device__ alignas(1024) __half g_Bh[(size_t)BATCH * NDIM * KDIM];
__device__ int g_tileCtr;        // reset by cvt kernel each launch

// ---------------------------------------------------------------------------
// PTX helpers — sm_90-class only (NO 'a'-suffix features; target is sm_103)
// ---------------------------------------------------------------------------
__device__ __forceinline__ uint32_t smem_u32(const void* p) {
    uint32_t a;
    asm("{ .reg .u64 t; cvta.to.shared.u64 t, %1; cvt.u32.u64 %0, t; }"
        : "=r"(a) : "l"(p));
    return a;
}

#define MBARRIER_INIT(addr, cnt) \
    asm volatile("mbarrier.init.shared.b64 [%0], %1;" :: "r"(addr), "r"(cnt) : "memory")

#define MBARRIER_EXPECT_TX(addr, bytes) \
    asm volatile("mbarrier.arrive.expect_tx.shared.b64 _, [%0], %1;" \
                 :: "r"(addr), "r"(bytes) : "memory")

#define MBAR_WAIT(addr, parity) do {                                          \
    asm volatile(                                                             \
        "{\n\t.reg .pred P1;\n\t"                                             \
        "WAIT_LOOP_%=:\n\t"                                                   \
        "mbarrier.try_wait.parity.acquire.cta.shared::cta.b64 P1, [%0], %1, 0x989680;\n\t" \
        "@P1 bra.uni WAIT_DONE_%=;\n\t"                                       \
        "bra.uni WAIT_LOOP_%=;\n\t"                                           \
        "WAIT_DONE_%=:\n\t}"                                                  \
        :: "r"((uint32_t)(addr)), "r"((uint32_t)(parity)) : "memory");        \
} while (0)

__device__ __forceinline__ void tma2d(uint32_t smem_dst, const CUtensorMap* map,
                                      int x, int y, uint32_t mbar) {
    asm volatile(
        "cp.async.bulk.tensor.2d.shared::cta.global.tile.mbarrier::complete_tx::bytes "
        "[%0], [%1, {%2, %3}], [%4];"
        :: "r"(smem_dst), "l"(map), "r"(x), "r"(y), "r"(mbar)
        : "memory");
}

__device__ __forceinline__ void ldsm_x4(uint32_t* r, uint32_t addr) {
    asm volatile("ldmatrix.sync.aligned.m8n8.x4.shared.b16 {%0,%1,%2,%3}, [%4];"
                 : "=r"(r[0]), "=r"(r[1]), "=r"(r[2]), "=r"(r[3]) : "r"(addr));
}

// fp16 inputs, fp32 accumulate
__device__ __forceinline__ void mma_f32acc(float* d, const uint32_t* a,
                                           uint32_t b0, uint32_t b1) {
    asm volatile(
        "mma.sync.aligned.m16n8k16.row.col.f32.f16.f16.f32 "
        "{%0,%1,%2,%3}, {%4,%5,%6,%7}, {%8,%9}, {%0,%1,%2,%3};"
        : "+f"(d[0]), "+f"(d[1]), "+f"(d[2]), "+f"(d[3])
        : "r"(a[0]), "r"(a[1]), "r"(a[2]), "r"(a[3]), "r"(b0), "r"(b1));
}

// ---------------------------------------------------------------------------
// Fused convert kernel:
//   blocks [0, 4096): B[b][k][n] -> g_Bh[b][n][k] fp16, 64x64 tile transpose
//                     (128B coalesced writes)
//   blocks [4096, 4608): A -> g_Ah fp16 (grid-stride)
// Also resets the GEMM tile counter (block 0).
// ---------------------------------------------------------------------------
#define NBLK_B 4096              // 4 batches * 32*32 tiles of 64x64
#define NBLK_A 512

__global__ void cvt_fused_kernel(const float* __restrict__ a,
                                 const float* __restrict__ bsrc) {
    const int bx = blockIdx.x;
    const int tid = threadIdx.x;

    if (bx == 0 && tid == 0) g_tileCtr = 0;

    if (bx < NBLK_B) {
        __shared__ float t[64][65];
        const int tile = bx & 1023;
        const int nb = tile & 31;            // 32 n-tiles of 64
        const int kb = tile >> 5;            // 32 k-tiles of 64
        const int b = bx >> 10;              // 4 batches
        const int n0 = nb * 64, k0 = kb * 64;
        const float* src = bsrc + (size_t)b * KDIM * NDIM;

        // Read: 64 rows x 64 floats; warp covers 2 rows x 16 float4 (256B runs)
        {
            const int colf4 = tid & 15;          // 16 float4 per row
            const int row0 = tid >> 4;           // 16 rows per pass
#pragma unroll
            for (int p = 0; p < 4; p++) {
                const int row = row0 + p * 16;
                float4 v = *(const float4*)&src[(size_t)(k0 + row) * NDIM
                                                + n0 + colf4 * 4];
                t[row][colf4 * 4 + 0] = v.x;
                t[row][colf4 * 4 + 1] = v.y;
                t[row][colf4 * 4 + 2] = v.z;
                t[row][colf4 * 4 + 3] = v.w;
            }
        }
        __syncthreads();

        // Write: 64 n-rows x 128B, 8 threads per row (uint4 each) — coalesced
        {
            const int kq = tid & 7;              // 8 halves per thread
            const int nr0 = tid >> 3;            // 32 n-rows per pass
            const size_t base = (size_t)b * NDIM * KDIM;
#pragma unroll
            for (int p = 0; p < 2; p++) {
                const int n = nr0 + p * 32;
                uint4 pk;
                __half2 h;
                h = __floats2half2_rn(t[kq * 8 + 0][n], t[kq * 8 + 1][n]);
                pk.x = *reinterpret_cast<uint32_t*>(&h);
                h = __floats2half2_rn(t[kq * 8 + 2][n], t[kq * 8 + 3][n]);
                pk.y = *reinterpret_cast<uint32_t*>(&h);
                h = __floats2half2_rn(t[kq * 8 + 4][n], t[kq * 8 + 5][n]);
                pk.z = *reinterpret_cast<uint32_t*>(&h);
                h = __floats2half2_rn(t[kq * 8 + 6][n], t[kq * 8 + 7][n]);
                pk.w = *reinterpret_cast<uint32_t*>(&h);
                const size_t off = base + (size_t)(n0 + n) * KDIM + k0 + kq * 8;
                *reinterpret_cast<uint4*>(&g_Bh[off]) = pk;
            }
        }
    } else {
        const size_t n4 = (size_t)BATCH * MDIM * KDIM / 4;
        const float4* a4 = (const float4*)a;
        uint2* hi = (uint2*)g_Ah;
        for (size_t i = (size_t)(bx - NBLK_B) * 256 + tid; i < n4;
             i += (size_t)NBLK_A * 256) {
            float4 v = a4[i];
            __half2 h01 = __floats2half2_rn(v.x, v.y);
            __half2 h23 = __floats2half2_rn(v.z, v.w);
            uint2 hv;
            hv.x = *reinterpret_cast<uint32_t*>(&h01);
            hv.y = *reinterpret_cast<uint32_t*>(&h23);
            hi[i] = hv;
        }
    }
}

// ---------------------------------------------------------------------------
// Persistent GEMM with dynamic tile stealing, 3-stage TMA pipeline.
// Deterministic: each tile computed exactly once.
// ---------------------------------------------------------------------------
__device__ __forceinline__ void tile_coords(int t, int& rowA, int& rowB) {
    const int tn = t & 31;            // 32 N-tiles of 64
    const int tm = (t >> 5) & 15;     // 16 M-tiles of 128
    const int bb = t >> 9;            // batch
    rowA = bb * MDIM + tm * TILE_M;
    rowB = bb * NDIM + tn * TILE_N;
}

__global__ void __launch_bounds__(256, 3) gemm_kernel(
    const __grid_constant__ CUtensorMap mAh,
    const __grid_constant__ CUtensorMap mBh,
    float* __restrict__ C)
{
    extern __shared__ char smem[];
    const uint32_t sb = smem_u32(smem);
    int* tileSlot = reinterpret_cast<int*>(smem + 64);  // [0]=cur, [1]=next
    const int tid = threadIdx.x;
    const int wid = tid >> 5;
    const int lane = tid & 31;
    const int warpM = wid & 3;        // 4 groups of 32 rows
    const int warpN = wid >> 2;       // 2 groups of 32 cols

    if (tid == 0) {
#pragma unroll
        for (int s = 0; s < STAGES; s++) MBARRIER_INIT(sb + 8 * s, 1);
        asm volatile("fence.proxy.async.shared::cta;" ::: "memory");
    }
    __syncthreads();

    // Grab first tile + prologue fill (3 stages, chunks 0..2)
    if (tid == 0) {
        int t0 = atomicAdd(&g_tileCtr, 1);   // < NTILES (grid 456 < 2048)
        tileSlot[0] = t0;
        int rowA, rowB;
        tile_coords(t0, rowA, rowB);
#pragma unroll
        for (int s = 0; s < STAGES; s++) {
            const uint32_t st = sb + SMEM_CTRL + s * STAGE_BYTES;
            MBARRIER_EXPECT_TX(sb + 8 * s, (uint32_t)STAGE_BYTES);
            tma2d(st + OFF_AH, &mAh, s * KC, rowA, sb + 8 * s);
            tma2d(st + OFF_BH, &mBh, s * KC, rowB, sb + 8 * s);
        }
    }
    __syncthreads();
    int curTile = tileSlot[0];

    // ldmatrix addressing (SW128 swizzle = XOR bits[6:4] with row&7)
    const int r15 = lane & 15;
    const int kh = lane >> 4;
    const uint32_t xorv = (uint32_t)((lane & 7) << 4);
    uint32_t kpart[4];
#pragma unroll
    for (int ks = 0; ks < 4; ks++)
        kpart[ks] = ((uint32_t)(ks * 32 + kh * 16)) ^ xorv;

    uint32_t aRowOff[2], bRowOff[2];
#pragma unroll
    for (int mt = 0; mt < 2; mt++)
        aRowOff[mt] = (uint32_t)(warpM * 32 + mt * 16 + r15) * 128;
#pragma unroll
    for (int ng = 0; ng < 2; ng++)
        bRowOff[ng] = (uint32_t)(warpN * 32 + ng * 16 + r15) * 128;

    int pf[STAGES] = {0, 0, 0};
    int sIdx = 0;                      // rotating stage index (global)

    while (curTile < NTILES_TOTAL) {
        float acc[2][4][4];
#pragma unroll
        for (int mt = 0; mt < 2; mt++)
#pragma unroll
            for (int nt = 0; nt < 4; nt++)
#pragma unroll
                for (int j = 0; j < 4; j++) acc[mt][nt][j] = 0.0f;

        for (int c = 0; c < CPT; c++) {
            const int s = sIdx;
            sIdx = (sIdx + 1 == STAGES) ? 0 : sIdx + 1;
            MBAR_WAIT(sb + 8 * s, pf[s]);
            pf[s] ^= 1;
            const uint32_t st = sb + SMEM_CTRL + s * STAGE_BYTES;

#pragma unroll
            for (int ks = 0; ks < 4; ks++) {
                uint32_t ah[2][4], bh[2][4];
#pragma unroll
                for (int mt = 0; mt < 2; mt++)
                    ldsm_x4(ah[mt], st + OFF_AH + aRowOff[mt] + kpart[ks]);
#pragma unroll
                for (int ng = 0; ng < 2; ng++)
                    ldsm_x4(bh[ng], st + OFF_BH + bRowOff[ng] + kpart[ks]);
#pragma unroll
                for (int mt = 0; mt < 2; mt++) {
#pragma unroll
                    for (int nt = 0; nt < 4; nt++) {
                        const int ng = nt >> 1;
                        const int o = nt & 1;
                        mma_f32acc(acc[mt][nt], ah[mt], bh[ng][o], bh[ng][o + 2]);
                    }
                }
            }

            __syncthreads();   // all warps done reading stage s
            if (tid == 0) {
                int cn = c + STAGES;                // refill chunk index
                int tTarget = curTile;
                if (cn >= CPT) {
                    if (cn == CPT)                  // first refill of next tile
                        tileSlot[1] = atomicAdd(&g_tileCtr, 1);  // steal it
                    tTarget = tileSlot[1];
                    cn -= CPT;
                }
                if (tTarget < NTILES_TOTAL) {
                    int rowA2, rowB2;
                    tile_coords(tTarget, rowA2, rowB2);
                    MBARRIER_EXPECT_TX(sb + 8 * s, (uint32_t)STAGE_BYTES);
                    tma2d(st + OFF_AH, &mAh, cn * KC, rowA2, sb + 8 * s);
                    tma2d(st + OFF_BH, &mBh, cn * KC, rowB2, sb + 8 * s);
                }
            }
        }

        // Epilogue for curTile (registers only)
        {
            int rowA, rowB;
            tile_coords(curTile, rowA, rowB);
            const int bb = curTile >> 9;
            const int cRow0 = (rowA - bb * MDIM) + warpM * 32 + (lane >> 2);
            const int cCol0 = (rowB - bb * NDIM) + warpN * 32 + (lane & 3) * 2;
            float* Cb = C + (size_t)bb * MDIM * NDIM;
#pragma unroll
            for (int mt = 0; mt < 2; mt++) {
                const int r0 = cRow0 + mt * 16;
                float* rp0 = Cb + (size_t)r0 * NDIM + cCol0;
                float* rp1 = Cb + (size_t)(r0 + 8) * NDIM + cCol0;
#pragma unroll
                for (int nt = 0; nt < 4; nt++) {
                    *reinterpret_cast<float2*>(rp0 + nt * 8) =
                        make_float2(acc[mt][nt][0], acc[mt][nt][1]);
                    *reinterpret_cast<float2*>(rp1 + nt * 8) =
                        make_float2(acc[mt][nt][2], acc[mt][nt][3]);
                }
            }
        }
        // tileSlot[1] was written by tid0 at c==CPT-STAGES (after that chunk's
        // __syncthreads); later chunks' barriers ordered it for all warps.
        curTile = tileSlot[1];
    }
}

// ---------------------------------------------------------------------------
// Host launch
// ---------------------------------------------------------------------------
typedef CUresult (*PFN_tmap_encode)(
    CUtensorMap*, CUtensorMapDataType, cuuint32_t, void*,
    const cuuint64_t*, const cuuint64_t*, const cuuint32_t*, const cuuint32_t*,
    CUtensorMapInterleave, CUtensorMapSwizzle, CUtensorMapL2promotion,
    CUtensorMapFloatOOBfill);

static void make_map_f16(PFN_tmap_encode enc, CUtensorMap* m, void* base,
                         cuuint64_t dim0, cuuint64_t dim1,
                         cuuint32_t box0, cuuint32_t box1) {
    cuuint64_t gd[2] = {dim0, dim1};
    cuuint64_t gs[1] = {dim0 * sizeof(__half)};
    cuuint32_t bd[2] = {box0, box1};
    cuuint32_t es[2] = {1, 1};
    enc(m, CU_TENSOR_MAP_DATA_TYPE_FLOAT16, 2, base, gd, gs, bd, es,
        CU_TENSOR_MAP_INTERLEAVE_NONE, CU_TENSOR_MAP_SWIZZLE_128B,
        CU_TENSOR_MAP_L2_PROMOTION_L2_128B, CU_TENSOR_MAP_FLOAT_OOB_FILL_NONE);
}

extern "C" void kernel_launch(void* const* d_in, const int* in_sizes, int n_in,
                              void* d_out, int out_size) {
    (void)in_sizes; (void)n_in; (void)out_size;
    const float* A = (const float*)d_in[0];
    const float* B = (const float*)d_in[1];
    float* C = (float*)d_out;

    cvt_fused_kernel<<<NBLK_B + NBLK_A, 256>>>(A, B);

    void *pAh = nullptr, *pBh = nullptr;
    cudaGetSymbolAddress(&pAh, g_Ah);
    cudaGetSymbolAddress(&pBh, g_Bh);

    void* fn = nullptr;
    cudaDriverEntryPointQueryResult qr;
    cudaGetDriverEntryPoint("cuTensorMapEncodeTiled", &fn, cudaEnableDefault, &qr);
    if (!fn) return;
    PFN_tmap_encode enc = (PFN_tmap_encode)fn;

    CUtensorMap mAh, mBh;
    make_map_f16(enc, &mAh, pAh, KDIM, (cuuint64_t)BATCH * MDIM, KC, TILE_M);
    make_map_f16(enc, &mBh, pBh, KDIM, (cuuint64_t)BATCH * NDIM, KC, TILE_N);

    cudaFuncSetAttribute(gemm_kernel, cudaFuncAttributeMaxDynamicSharedMemorySize,
                         SMEM_TOTAL);
    gemm_kernel<<<GRID_X, 256, SMEM_TOTAL>>>(mAh, mBh, C);
}

// round 15
// speedup vs baseline: 1.0708x; 1.0708x over previous
#include <cuda_runtime.h>
#include <cuda.h>
#include <cuda_fp16.h>
#include <cstdint>
#include <cstddef>

// Problem dims (fixed by the dataset)
#define BATCH 4
#define MDIM 2048
#define NDIM 2048
#define KDIM 2048

// GEMM tiling: EXACT R13 configuration (best measured GEMM: 166.3us):
// 128x64 tile, 8 warps 4Mx2N, warp tile 32x32, lockstep pipeline,
// occupancy 3 = 24 warps/SM, dynamic tile stealing, 2-stage TMA pipeline.
#define TILE_M 128
#define TILE_N 64
#define KC 64                    // K per chunk: 1 SW128 atom
#define CPT 32                   // chunks per tile
#define STAGES 2
#define NTILES_TOTAL 2048        // 32 * 16 * 4
#define GRID_X 456               // 3 * 152 SMs (GB300)

// Per-stage SMEM: A 16KB + B 8KB
#define OFF_AH 0
#define OFF_BH 16384
#define STAGE_BYTES 24576
#define SMEM_CTRL 1024
#define SMEM_TOTAL (SMEM_CTRL + STAGES * STAGE_BYTES)   // 50176 (x3 CTAs/SM)

// ---------------------------------------------------------------------------
// Scratch: fp16 of A [B,M,K]; B transposed to [B,N,K] (K-major)
// ---------------------------------------------------------------------------
__device__ alignas(1024) __half g_Ah[(size_t)BATCH * MDIM * KDIM];
__device__ alignas(1024) __half g_Bh[(size_t)BATCH * NDIM * KDIM];
__device__ int g_tileCtr;        // reset by cvt kernel each launch

// ---------------------------------------------------------------------------
// PTX helpers — sm_90-class only (NO 'a'-suffix features; target is sm_103)
// ---------------------------------------------------------------------------
__device__ __forceinline__ uint32_t smem_u32(const void* p) {
    uint32_t a;
    asm("{ .reg .u64 t; cvta.to.shared.u64 t, %1; cvt.u32.u64 %0, t; }"
        : "=r"(a) : "l"(p));
    return a;
}

#define MBARRIER_INIT(addr, cnt) \
    asm volatile("mbarrier.init.shared.b64 [%0], %1;" :: "r"(addr), "r"(cnt) : "memory")

#define MBARRIER_EXPECT_TX(addr, bytes) \
    asm volatile("mbarrier.arrive.expect_tx.shared.b64 _, [%0], %1;" \
                 :: "r"(addr), "r"(bytes) : "memory")

#define MBAR_WAIT(addr, parity) do {                                          \
    asm volatile(                                                             \
        "{\n\t.reg .pred P1;\n\t"                                             \
        "WAIT_LOOP_%=:\n\t"                                                   \
        "mbarrier.try_wait.parity.acquire.cta.shared::cta.b64 P1, [%0], %1, 0x989680;\n\t" \
        "@P1 bra.uni WAIT_DONE_%=;\n\t"                                       \
        "bra.uni WAIT_LOOP_%=;\n\t"                                           \
        "WAIT_DONE_%=:\n\t}"                                                  \
        :: "r"((uint32_t)(addr)), "r"((uint32_t)(parity)) : "memory");        \
} while (0)

__device__ __forceinline__ void tma2d(uint32_t smem_dst, const CUtensorMap* map,
                                      int x, int y, uint32_t mbar) {
    asm volatile(
        "cp.async.bulk.tensor.2d.shared::cta.global.tile.mbarrier::complete_tx::bytes "
        "[%0], [%1, {%2, %3}], [%4];"
        :: "r"(smem_dst), "l"(map), "r"(x), "r"(y), "r"(mbar)
        : "memory");
}

__device__ __forceinline__ void ldsm_x4(uint32_t* r, uint32_t addr) {
    asm volatile("ldmatrix.sync.aligned.m8n8.x4.shared.b16 {%0,%1,%2,%3}, [%4];"
                 : "=r"(r[0]), "=r"(r[1]), "=r"(r[2]), "=r"(r[3]) : "r"(addr));
}

// fp16 inputs, fp32 accumulate
__device__ __forceinline__ void mma_f32acc(float* d, const uint32_t* a,
                                           uint32_t b0, uint32_t b1) {
    asm volatile(
        "mma.sync.aligned.m16n8k16.row.col.f32.f16.f16.f32 "
        "{%0,%1,%2,%3}, {%4,%5,%6,%7}, {%8,%9}, {%0,%1,%2,%3};"
        : "+f"(d[0]), "+f"(d[1]), "+f"(d[2]), "+f"(d[3])
        : "r"(a[0]), "r"(a[1]), "r"(a[2]), "r"(a[3]), "r"(b0), "r"(b1));
}

// ---------------------------------------------------------------------------
// Fused convert kernel (R14 version — coalesced 64x64 B-transpose):
//   blocks [0, 4096): B[b][k][n] -> g_Bh[b][n][k] fp16 (128B coalesced writes)
//   blocks [4096, 4608): A -> g_Ah fp16 (grid-stride)
// Also resets the GEMM tile counter (block 0).
// ---------------------------------------------------------------------------
#define NBLK_B 4096              // 4 batches * 32*32 tiles of 64x64
#define NBLK_A 512

__global__ void cvt_fused_kernel(const float* __restrict__ a,
                                 const float* __restrict__ bsrc) {
    const int bx = blockIdx.x;
    const int tid = threadIdx.x;

    if (bx == 0 && tid == 0) g_tileCtr = 0;

    if (bx < NBLK_B) {
        __shared__ float t[64][65];
        const int tile = bx & 1023;
        const int nb = tile & 31;            // 32 n-tiles of 64
        const int kb = tile >> 5;            // 32 k-tiles of 64
        const int b = bx >> 10;              // 4 batches
        const int n0 = nb * 64, k0 = kb * 64;
        const float* src = bsrc + (size_t)b * KDIM * NDIM;

        // Read: 64 rows x 64 floats; warp covers 2 rows x 16 float4 (256B runs)
        {
            const int colf4 = tid & 15;          // 16 float4 per row
            const int row0 = tid >> 4;           // 16 rows per pass
#pragma unroll
            for (int p = 0; p < 4; p++) {
                const int row = row0 + p * 16;
                float4 v = *(const float4*)&src[(size_t)(k0 + row) * NDIM
                                                + n0 + colf4 * 4];
                t[row][colf4 * 4 + 0] = v.x;
                t[row][colf4 * 4 + 1] = v.y;
                t[row][colf4 * 4 + 2] = v.z;
                t[row][colf4 * 4 + 3] = v.w;
            }
        }
        __syncthreads();

        // Write: 64 n-rows x 128B, 8 threads per row (uint4 each) — coalesced
        {
            const int kq = tid & 7;              // 8 halves per thread
            const int nr0 = tid >> 3;            // 32 n-rows per pass
            const size_t base = (size_t)b * NDIM * KDIM;
#pragma unroll
            for (int p = 0; p < 2; p++) {
                const int n = nr0 + p * 32;
                uint4 pk;
                __half2 h;
                h = __floats2half2_rn(t[kq * 8 + 0][n], t[kq * 8 + 1][n]);
                pk.x = *reinterpret_cast<uint32_t*>(&h);
                h = __floats2half2_rn(t[kq * 8 + 2][n], t[kq * 8 + 3][n]);
                pk.y = *reinterpret_cast<uint32_t*>(&h);
                h = __floats2half2_rn(t[kq * 8 + 4][n], t[kq * 8 + 5][n]);
                pk.z = *reinterpret_cast<uint32_t*>(&h);
                h = __floats2half2_rn(t[kq * 8 + 6][n], t[kq * 8 + 7][n]);
                pk.w = *reinterpret_cast<uint32_t*>(&h);
                const size_t off = base + (size_t)(n0 + n) * KDIM + k0 + kq * 8;
                *reinterpret_cast<uint4*>(&g_Bh[off]) = pk;
            }
        }
    } else {
        const size_t n4 = (size_t)BATCH * MDIM * KDIM / 4;
        const float4* a4 = (const float4*)a;
        uint2* hi = (uint2*)g_Ah;
        for (size_t i = (size_t)(bx - NBLK_B) * 256 + tid; i < n4;
             i += (size_t)NBLK_A * 256) {
            float4 v = a4[i];
            __half2 h01 = __floats2half2_rn(v.x, v.y);
            __half2 h23 = __floats2half2_rn(v.z, v.w);
            uint2 hv;
            hv.x = *reinterpret_cast<uint32_t*>(&h01);
            hv.y = *reinterpret_cast<uint32_t*>(&h23);
            hi[i] = hv;
        }
    }
}

// ---------------------------------------------------------------------------
// Persistent GEMM with dynamic tile stealing (EXACT R13 main loop).
// Deterministic: each tile computed exactly once.
// ---------------------------------------------------------------------------
__device__ __forceinline__ void tile_coords(int t, int& rowA, int& rowB) {
    const int tn = t & 31;            // 32 N-tiles of 64
    const int tm = (t >> 5) & 15;     // 16 M-tiles of 128
    const int bb = t >> 9;            // batch
    rowA = bb * MDIM + tm * TILE_M;
    rowB = bb * NDIM + tn * TILE_N;
}

__global__ void __launch_bounds__(256, 3) gemm_kernel(
    const __grid_constant__ CUtensorMap mAh,
    const __grid_constant__ CUtensorMap mBh,
    float* __restrict__ C)
{
    extern __shared__ char smem[];
    const uint32_t sb = smem_u32(smem);
    int* tileSlot = reinterpret_cast<int*>(smem + 64);  // [0]=cur, [1]=next
    const int tid = threadIdx.x;
    const int wid = tid >> 5;
    const int lane = tid & 31;
    const int warpM = wid & 3;        // 4 groups of 32 rows
    const int warpN = wid >> 2;       // 2 groups of 32 cols

    if (tid == 0) {
        MBARRIER_INIT(sb + 0, 1);
        MBARRIER_INIT(sb + 8, 1);
        asm volatile("fence.proxy.async.shared::cta;" ::: "memory");
    }
    __syncthreads();

    // Grab first tile + prologue fill (both stages, chunks 0 and 1)
    if (tid == 0) {
        int t0 = atomicAdd(&g_tileCtr, 1);   // < NTILES (grid 456 < 2048)
        tileSlot[0] = t0;
        int rowA, rowB;
        tile_coords(t0, rowA, rowB);
#pragma unroll
        for (int s = 0; s < STAGES; s++) {
            const uint32_t st = sb + SMEM_CTRL + s * STAGE_BYTES;
            MBARRIER_EXPECT_TX(sb + 8 * s, (uint32_t)STAGE_BYTES);
            tma2d(st + OFF_AH, &mAh, s * KC, rowA, sb + 8 * s);
            tma2d(st + OFF_BH, &mBh, s * KC, rowB, sb + 8 * s);
        }
    }
    __syncthreads();
    int curTile = tileSlot[0];

    // ldmatrix addressing (SW128 swizzle = XOR bits[6:4] with row&7)
    const int r15 = lane & 15;
    const int kh = lane >> 4;
    const uint32_t xorv = (uint32_t)((lane & 7) << 4);
    uint32_t kpart[4];
#pragma unroll
    for (int ks = 0; ks < 4; ks++)
        kpart[ks] = ((uint32_t)(ks * 32 + kh * 16)) ^ xorv;

    uint32_t aRowOff[2], bRowOff[2];
#pragma unroll
    for (int mt = 0; mt < 2; mt++)
        aRowOff[mt] = (uint32_t)(warpM * 32 + mt * 16 + r15) * 128;
#pragma unroll
    for (int ng = 0; ng < 2; ng++)
        bRowOff[ng] = (uint32_t)(warpN * 32 + ng * 16 + r15) * 128;

    int pf[STAGES] = {0, 0};
    int g = 0;                         // global chunk counter (stage parity)

    while (curTile < NTILES_TOTAL) {
        float acc[2][4][4];
#pragma unroll
        for (int mt = 0; mt < 2; mt++)
#pragma unroll
            for (int nt = 0; nt < 4; nt++)
#pragma unroll
                for (int j = 0; j < 4; j++) acc[mt][nt][j] = 0.0f;

        for (int c = 0; c < CPT; c++, g++) {
            const int s = g & 1;
            MBAR_WAIT(sb + 8 * s, pf[s]);
            pf[s] ^= 1;
            const uint32_t st = sb + SMEM_CTRL + s * STAGE_BYTES;

#pragma unroll
            for (int ks = 0; ks < 4; ks++) {
                uint32_t ah[2][4], bh[2][4];
#pragma unroll
                for (int mt = 0; mt < 2; mt++)
                    ldsm_x4(ah[mt], st + OFF_AH + aRowOff[mt] + kpart[ks]);
#pragma unroll
                for (int ng = 0; ng < 2; ng++)
                    ldsm_x4(bh[ng], st + OFF_BH + bRowOff[ng] + kpart[ks]);
#pragma unroll
                for (int mt = 0; mt < 2; mt++) {
#pragma unroll
                    for (int nt = 0; nt < 4; nt++) {
                        const int ng = nt >> 1;
                        const int o = nt & 1;
                        mma_f32acc(acc[mt][nt], ah[mt], bh[ng][o], bh[ng][o + 2]);
                    }
                }
            }

            __syncthreads();   // all warps done reading stage s
            if (tid == 0) {
                int cn = c + STAGES;
                int tTarget = curTile;
                if (cn >= CPT) {
                    if (cn == CPT)               // first refill of next tile:
                        tileSlot[1] = atomicAdd(&g_tileCtr, 1);  // steal it
                    tTarget = tileSlot[1];
                    cn -= CPT;
                }
                if (tTarget < NTILES_TOTAL) {
                    int rowA2, rowB2;
                    tile_coords(tTarget, rowA2, rowB2);
                    MBARRIER_EXPECT_TX(sb + 8 * s, (uint32_t)STAGE_BYTES);
                    tma2d(st + OFF_AH, &mAh, cn * KC, rowA2, sb + 8 * s);
                    tma2d(st + OFF_BH, &mBh, cn * KC, rowB2, sb + 8 * s);
                }
            }
        }

        // Epilogue for curTile (registers only)
        {
            int rowA, rowB;
            tile_coords(curTile, rowA, rowB);
            const int bb = curTile >> 9;
            const int cRow0 = (rowA - bb * MDIM) + warpM * 32 + (lane >> 2);
            const int cCol0 = (rowB - bb * NDIM) + warpN * 32 + (lane & 3) * 2;
            float* Cb = C + (size_t)bb * MDIM * NDIM;
#pragma unroll
            for (int mt = 0; mt < 2; mt++) {
                const int r0 = cRow0 + mt * 16;
                float* rp0 = Cb + (size_t)r0 * NDIM + cCol0;
                float* rp1 = Cb + (size_t)(r0 + 8) * NDIM + cCol0;
#pragma unroll
                for (int nt = 0; nt < 4; nt++) {
                    *reinterpret_cast<float2*>(rp0 + nt * 8) =
                        make_float2(acc[mt][nt][0], acc[mt][nt][1]);
                    *reinterpret_cast<float2*>(rp1 + nt * 8) =
                        make_float2(acc[mt][nt][2], acc[mt][nt][3]);
                }
            }
        }
        // tileSlot[1] was written by tid0 at c==CPT-2 (after that chunk's
        // __syncthreads); the c==CPT-1 __syncthreads ordered it for all.
        curTile = tileSlot[1];
    }
}

// ---------------------------------------------------------------------------
// Host launch
// ---------------------------------------------------------------------------
typedef CUresult (*PFN_tmap_encode)(
    CUtensorMap*, CUtensorMapDataType, cuuint32_t, void*,
    const cuuint64_t*, const cuuint64_t*, const cuuint32_t*, const cuuint32_t*,
    CUtensorMapInterleave, CUtensorMapSwizzle, CUtensorMapL2promotion,
    CUtensorMapFloatOOBfill);

static void make_map_f16(PFN_tmap_encode enc, CUtensorMap* m, void* base,
                         cuuint64_t dim0, cuuint64_t dim1,
                         cuuint32_t box0, cuuint32_t box1) {
    cuuint64_t gd[2] = {dim0, dim1};
    cuuint64_t gs[1] = {dim0 * sizeof(__half)};
    cuuint32_t bd[2] = {box0, box1};
    cuuint32_t es[2] = {1, 1};
    enc(m, CU_TENSOR_MAP_DATA_TYPE_FLOAT16, 2, base, gd, gs, bd, es,
        CU_TENSOR_MAP_INTERLEAVE_NONE, CU_TENSOR_MAP_SWIZZLE_128B,
        CU_TENSOR_MAP_L2_PROMOTION_L2_128B, CU_TENSOR_MAP_FLOAT_OOB_FILL_NONE);
}

extern "C" void kernel_launch(void* const* d_in, const int* in_sizes, int n_in,
                              void* d_out, int out_size) {
    (void)in_sizes; (void)n_in; (void)out_size;
    const float* A = (const float*)d_in[0];
    const float* B = (const float*)d_in[1];
    float* C = (float*)d_out;

    cvt_fused_kernel<<<NBLK_B + NBLK_A, 256>>>(A, B);

    void *pAh = nullptr, *pBh = nullptr;
    cudaGetSymbolAddress(&pAh, g_Ah);
    cudaGetSymbolAddress(&pBh, g_Bh);

    void* fn = nullptr;
    cudaDriverEntryPointQueryResult qr;
    cudaGetDriverEntryPoint("cuTensorMapEncodeTiled", &fn, cudaEnableDefault, &qr);
    if (!fn) return;
    PFN_tmap_encode enc = (PFN_tmap_encode)fn;

    CUtensorMap mAh, mBh;
    make_map_f16(enc, &mAh, pAh, KDIM, (cuuint64_t)BATCH * MDIM, KC, TILE_M);
    make_map_f16(enc, &mBh, pBh, KDIM, (cuuint64_t)BATCH * NDIM, KC, TILE_N);

    cudaFuncSetAttribute(gemm_kernel, cudaFuncAttributeMaxDynamicSharedMemorySize,
                         SMEM_TOTAL);
    gemm_kernel<<<GRID_X, 256, SMEM_TOTAL>>>(mAh, mBh, C);
}